// round 12
// baseline (speedup 1.0000x reference)
#include <cuda_runtime.h>
#include <math.h>

#define L     4096
#define BATCH 16
#define CH    512     // H*E = 8*64
#define TOPK  24      // int(3.0 * ln(4096)) = 24
#define FPSCALE 1048576.0f   // 2^20 fixed point for deterministic accumulation
#define CPB   8       // channels per CTA in k_fft
#define PAD(i) ((i) + ((i) >> 4))
#define PBUF  4352    // PAD(4095)=4350 -> 4352 float2

// ---------------- scratch (device globals; no allocs) ----------------
__device__ float2    d_z[(size_t)BATCH * CH * L];   // packed z = q + i*k, (B,C,L)
__device__ long long d_S[BATCH * L * 2];            // per-b cross spectrum (f<=2048 used)
__device__ float2    d_tw[L];                       // e^{-2pi i m / L}
__device__ float     d_mean[BATCH * L];
__device__ int       d_idx[TOPK];
__device__ float     d_w[BATCH * TOPK];
__device__ int       d_done;                        // irfft completion counter

// ---------------- complex helpers ----------------
__device__ __forceinline__ float2 cadd(float2 a, float2 b){ return make_float2(a.x+b.x, a.y+b.y); }
__device__ __forceinline__ float2 csub(float2 a, float2 b){ return make_float2(a.x-b.x, a.y-b.y); }
__device__ __forceinline__ float2 cmul(float2 a, float2 b){
    return make_float2(a.x*b.x - a.y*b.y, a.x*b.y + a.y*b.x);
}

// ---------------- K1: transpose (B,L,C)->(B,C,L) + fused init ----------------
__global__ void k_transpose(const float* __restrict__ q, const float* __restrict__ k) {
    __shared__ float2 tile[32][33];   // [t_local][c_local], padded
    int b  = blockIdx.z;
    int t0 = blockIdx.x * 32;
    int c0 = blockIdx.y * 32;
    int tx = threadIdx.x, ty = threadIdx.y;
    int tid = ty * 32 + tx;

    // fused init: y==0 blocks zero d_S; block (0,0,0) builds twiddles + counter
    if (blockIdx.y == 0) {
        int blk = blockIdx.x + (L / 32) * blockIdx.z;   // 0..2047
        int gid = blk * 256 + tid;
        if (gid < BATCH * L * 2) d_S[gid] = 0;
        if (blk == 0) {
            for (int i = tid; i < L; i += 256) {
                double th = -2.0 * 3.14159265358979323846 * (double)i / (double)L;
                d_tw[i] = make_float2((float)cos(th), (float)sin(th));
            }
            if (tid == 0) d_done = 0;
        }
    }

    #pragma unroll
    for (int r = 0; r < 4; r++) {
        int t = t0 + ty + r * 8;
        size_t idx = ((size_t)b * L + t) * CH + c0 + tx;   // coalesced over c
        tile[ty + r * 8][tx] = make_float2(q[idx], k[idx]);
    }
    __syncthreads();
    #pragma unroll
    for (int r = 0; r < 4; r++) {
        int c = c0 + ty + r * 8;
        d_z[((size_t)b * CH + c) * L + t0 + tx] = tile[tx][ty + r * 8];  // coalesced over t
    }
}

// ---------------- register-resident 16-point DFT (natural order in/out) --------
__device__ __forceinline__ void dft16(float2* a) {
    const float2 W16[10] = {
        { 1.0f, 0.0f},
        { 0.9238795325f,-0.3826834324f},
        { 0.7071067812f,-0.7071067812f},
        { 0.3826834324f,-0.9238795325f},
        { 0.0f,-1.0f},
        {-0.3826834324f,-0.9238795325f},
        {-0.7071067812f,-0.7071067812f},
        {-0.9238795325f,-0.3826834324f},
        {-1.0f, 0.0f},
        {-0.9238795325f, 0.3826834324f}
    };
    float2 bb[4][4];
    #pragma unroll
    for (int n1 = 0; n1 < 4; n1++) {
        float2 x0 = a[n1], x1 = a[n1+4], x2 = a[n1+8], x3 = a[n1+12];
        float2 apc = cadd(x0,x2), amc = csub(x0,x2);
        float2 bpd = cadd(x1,x3), bmd = csub(x1,x3);
        float2 mjb = make_float2(bmd.y, -bmd.x);   // -i*(x1-x3)
        bb[n1][0] = cadd(apc,bpd);
        bb[n1][1] = cadd(amc,mjb);
        bb[n1][2] = csub(apc,bpd);
        bb[n1][3] = csub(amc,mjb);
    }
    #pragma unroll
    for (int k1 = 0; k1 < 4; k1++) {
        float2 y0 = bb[0][k1];
        float2 y1 = cmul(bb[1][k1], W16[k1]);
        float2 y2 = cmul(bb[2][k1], W16[2*k1]);
        float2 y3 = cmul(bb[3][k1], W16[3*k1]);
        float2 apc = cadd(y0,y2), amc = csub(y0,y2);
        float2 bpd = cadd(y1,y3), bmd = csub(y1,y3);
        float2 mjb = make_float2(bmd.y, -bmd.x);
        a[k1]      = cadd(apc,bpd);
        a[k1+4]    = cadd(amc,mjb);
        a[k1+8]    = csub(apc,bpd);
        a[k1+12]   = csub(amc,mjb);
    }
}

// Stockham stage store: out[u + 15*ps + s*jj] = tw4096[jj*ps] * r[jj]
__device__ __forceinline__ void stage_store(const float2* r, float2* buf, int u, int s) {
    int ps = (u / s) * s;
    float2 P[4], A[4];
    P[0] = make_float2(1.f, 0.f);
    P[1] = d_tw[ps];
    P[2] = cmul(P[1], P[1]);
    P[3] = cmul(P[2], P[1]);
    A[0] = make_float2(1.f, 0.f);
    A[1] = d_tw[4  * ps];
    A[2] = d_tw[8  * ps];
    A[3] = d_tw[12 * ps];
    int base = u + 15 * ps;
    #pragma unroll
    for (int jj = 0; jj < 16; jj++) {
        float2 w = cmul(A[jj >> 2], P[jj & 3]);
        buf[PAD(base + s * jj)] = cmul(w, r[jj]);
    }
}

// ---------------- K2: pipelined FFT + half-spectrum accumulate ----------------
// Stage-2 output is register-resident: X[tid+256*j] == r[j]. Only the upper half
// (slots 2048..4095 = r[8..15]) is stored to smem, to serve Hermitian mirrors.
__global__ void __launch_bounds__(256, 3) k_fft() {
    extern __shared__ float2 sm[];
    float2* bufA = sm;
    float2* bufB = sm + PBUF;
    int tid = threadIdx.x;
    int blk = blockIdx.x;            // 1024 blocks = 16 b * 64 groups
    int b   = blk >> 6;
    int c0  = (blk & 63) * CPB;

    float accx[8], accy[8], accN = 0.f;
    #pragma unroll
    for (int j = 0; j < 8; j++) { accx[j] = 0.f; accy[j] = 0.f; }

    const float2* zbase = d_z + ((size_t)(b * CH + c0)) * L;
    float2 r[16];
    // prologue: load channel 0
    #pragma unroll
    for (int j = 0; j < 16; j++) r[j] = zbase[tid + 256 * j];

    for (int cc = 0; cc < CPB; cc++) {
        float2* X = (cc & 1) ? bufB : bufA;   // parity ping-pong
        float2* Y = (cc & 1) ? bufA : bufB;
        // stage 0 (s=1): r (preloaded) -> X
        dft16(r);
        stage_store(r, X, tid, 1);
        __syncthreads();
        // stage 1 (s=16): X -> Y
        #pragma unroll
        for (int j = 0; j < 16; j++) r[j] = X[PAD(tid + 256 * j)];
        dft16(r);
        stage_store(r, Y, tid, 16);
        __syncthreads();
        // stage 2 (s=256, ps=0, twiddles=1): Y -> regs; r[j] == X[tid+256*j]
        #pragma unroll
        for (int j = 0; j < 16; j++) r[j] = Y[PAD(tid + 256 * j)];
        dft16(r);
        if (tid == 0) accN += r[8].x * r[8].y;     // Nyquist X[2048], own reg
        // store upper half only (mirror source for f in [1,2047])
        #pragma unroll
        for (int jj = 8; jj < 16; jj++) X[PAD(tid + 256 * jj)] = r[jj];
        __syncthreads();
        // prefetch next channel's upper regs (dead after store)
        if (cc + 1 < CPB) {
            const float2* zr = zbase + ((size_t)(cc + 1)) * L;
            #pragma unroll
            for (int j = 8; j < 16; j++) r[j] = zr[tid + 256 * j];
        }
        // unpack z=q+ik for f in [0,2047]: Zf from regs, Zr from stored upper half
        #pragma unroll
        for (int j = 0; j < 8; j++) {
            int i = tid + 256 * j;                 // 0..2047
            float2 Zf = r[j];
            int m = (L - i) & (L - 1);             // 4096-i (>=2048 for i>=1)
            float2 Zr = X[PAD(m)];
            if (i == 0) Zr = Zf;                   // f=0 self-mirror
            float qx = 0.5f * (Zf.x + Zr.x), qy =  0.5f * (Zf.y - Zr.y);
            float kx = 0.5f * (Zf.y + Zr.y), ky = -0.5f * (Zf.x - Zr.x);
            accx[j] += qx * kx + qy * ky;
            accy[j] += qy * kx - qx * ky;
        }
        // prefetch next channel's lower regs
        if (cc + 1 < CPB) {
            const float2* zr = zbase + ((size_t)(cc + 1)) * L;
            #pragma unroll
            for (int j = 0; j < 8; j++) r[j] = zr[tid + 256 * j];
        }
        // no trailing sync: next stage0 writes the OTHER buffer; its post-store
        // sync orders stage1's write to this buffer after all unpack reads.
    }

    long long* Sb = d_S + b * L * 2;
    #pragma unroll
    for (int j = 0; j < 8; j++) {
        int i = tid + 256 * j;
        atomicAdd((unsigned long long*)&Sb[2 * i],
                  (unsigned long long)(long long)llrintf(accx[j] * FPSCALE));
        atomicAdd((unsigned long long*)&Sb[2 * i + 1],
                  (unsigned long long)(long long)llrintf(accy[j] * FPSCALE));
    }
    if (tid == 0)
        atomicAdd((unsigned long long*)&Sb[2 * 2048],
                  (unsigned long long)(long long)llrintf(accN * FPSCALE));
}

// ---------------- radix-4 Stockham FFT (for K3; 16 CTAs, negligible) ------
__device__ __forceinline__ void fft4096_r4(float2* x0, float2* y0,
                                           const float2* __restrict__ tw, int tid) {
    float2* x = x0;
    float2* y = y0;
    #pragma unroll
    for (int stage = 0; stage < 6; stage++) {
        int s = 1 << (2 * stage);
        #pragma unroll
        for (int uu = 0; uu < 4; uu++) {
            int u  = tid + uu * 256;
            int ps = u & ~(s - 1);
            float2 a = x[u];
            float2 b = x[u + 1024];
            float2 c = x[u + 2048];
            float2 d = x[u + 3072];
            float2 apc = cadd(a, c), amc = csub(a, c);
            float2 bpd = cadd(b, d), bmd = csub(b, d);
            float2 jbmd = make_float2(-bmd.y, bmd.x);
            float2 w1 = tw[ps], w2 = tw[2 * ps], w3 = tw[3 * ps];
            int o = u + 3 * ps;
            y[o]         = cadd(apc, bpd);
            y[o + s]     = cmul(w1, csub(amc, jbmd));
            y[o + 2 * s] = cmul(w2, csub(apc, bpd));
            y[o + 3 * s] = cmul(w3, cadd(amc, jbmd));
        }
        __syncthreads();
        float2* t = x; x = y; y = t;
    }
}

// ---------------- K3: inverse transform -> mean_value; last CTA does top-k -----
__global__ void k_irfft_topk() {
    extern __shared__ float2 sm[];
    float2* A   = sm;
    float2* B   = sm + L;
    float2* tws = sm + 2 * L;
    int tid = threadIdx.x;
    int b   = blockIdx.x;
    const long long* Sb = d_S + b * L * 2;
    const float c1 = 1.0f / FPSCALE;
    for (int i = tid; i < L; i += 256) {
        int m = (i <= 2048) ? i : (L - i);       // stored half-spectrum index
        float sx = (float)Sb[2 * m]     * c1;
        float sy = (float)Sb[2 * m + 1] * c1;
        float sgn = (i <= 2048) ? -1.f : 1.f;    // feed A = conj(S[i])
        A[i] = make_float2(sx, sgn * sy);
        tws[i] = d_tw[i];
    }
    __syncthreads();
    fft4096_r4(A, B, tws, tid);
    const float c2 = 1.0f / ((float)L * (float)CH);
    for (int i = tid; i < L; i += 256) d_mean[b * L + i] = A[i].x * c2;

    // completion counter; last CTA runs top-k + softmax
    __threadfence();
    __syncthreads();
    __shared__ int slast;
    if (tid == 0) slast = atomicAdd(&d_done, 1);
    __syncthreads();
    if (slast != BATCH - 1) return;
    __threadfence();

    float* cm = (float*)B;                      // reuse 32 KB of dynamic smem
    __shared__ float rv[256];
    __shared__ int   ri[256];
    __shared__ int   sidx[TOPK];
    for (int i = tid; i < L; i += 256) {
        float s = 0.0f;
        #pragma unroll
        for (int bb = 0; bb < BATCH; bb++) s += d_mean[bb * L + i];
        cm[i] = s;
    }
    __syncthreads();
    for (int it = 0; it < TOPK; it++) {
        float best = -1e30f; int bi = 0;
        for (int i = tid; i < L; i += 256) {
            float vv = cm[i];
            if (vv > best) { best = vv; bi = i; }
        }
        rv[tid] = best; ri[tid] = bi;
        __syncthreads();
        for (int off = 128; off > 0; off >>= 1) {
            if (tid < off) {
                if (rv[tid + off] > rv[tid] ||
                    (rv[tid + off] == rv[tid] && ri[tid + off] < ri[tid])) {
                    rv[tid] = rv[tid + off]; ri[tid] = ri[tid + off];
                }
            }
            __syncthreads();
        }
        if (tid == 0) { sidx[it] = ri[0]; cm[ri[0]] = -1e30f; }
        __syncthreads();
    }
    if (tid < TOPK) d_idx[tid] = sidx[tid];
    if (tid < BATCH) {
        int bb = tid;
        float vals[TOPK]; float mx = -1e30f;
        #pragma unroll
        for (int i = 0; i < TOPK; i++) { vals[i] = d_mean[bb * L + sidx[i]]; mx = fmaxf(mx, vals[i]); }
        float ssum = 0.0f;
        #pragma unroll
        for (int i = 0; i < TOPK; i++) { vals[i] = expf(vals[i] - mx); ssum += vals[i]; }
        #pragma unroll
        for (int i = 0; i < TOPK; i++) d_w[bb * TOPK + i] = vals[i] / ssum;
    }
}

// ---------------- K5: weighted shifted aggregation (coalesced L2 streaming) ----
__global__ void k_agg(const float4* __restrict__ v4, float4* __restrict__ o4) {
    __shared__ int   si[TOPK];
    __shared__ float sw[TOPK];
    int t = blockIdx.x, b = blockIdx.y, tid = threadIdx.x;   // 128 threads, float4 over 512 ch
    if (tid < TOPK) { si[tid] = d_idx[tid]; sw[tid] = d_w[b * TOPK + tid]; }
    __syncthreads();
    const float4* vb = v4 + (size_t)b * L * 128;
    float4 acc = make_float4(0.f, 0.f, 0.f, 0.f);
    #pragma unroll
    for (int i = 0; i < TOPK; i++) {
        int tt = (t + si[i]) & (L - 1);
        float4 vv = vb[tt * 128 + tid];
        float w = sw[i];
        acc.x += w * vv.x; acc.y += w * vv.y; acc.z += w * vv.z; acc.w += w * vv.w;
    }
    o4[((size_t)b * L + t) * 128 + tid] = acc;
}

// ---------------- launcher ----------------
extern "C" void kernel_launch(void* const* d_in, const int* in_sizes, int n_in,
                              void* d_out, int out_size) {
    const float* q = (const float*)d_in[0];
    const float* k = (const float*)d_in[1];
    const float* v = (const float*)d_in[2];

    const int smem_fft  = 2 * PBUF * sizeof(float2);   // 69,632 B
    const int smem_ifft = 3 * L * sizeof(float2);      // 96 KB
    cudaFuncSetAttribute(k_fft,        cudaFuncAttributeMaxDynamicSharedMemorySize, smem_fft);
    cudaFuncSetAttribute(k_irfft_topk, cudaFuncAttributeMaxDynamicSharedMemorySize, smem_ifft);

    k_transpose<<<dim3(L / 32, CH / 32, BATCH), dim3(32, 8, 1)>>>(q, k); // launch 1
    k_fft<<<(BATCH * CH) / CPB, 256, smem_fft>>>();                      // launch 2
    k_irfft_topk<<<BATCH, 256, smem_ifft>>>();                           // launch 3
    k_agg<<<dim3(L, BATCH), 128>>>((const float4*)v, (float4*)d_out);    // launch 4 (ncu slot)
}

// round 14
// speedup vs baseline: 1.1277x; 1.1277x over previous
#include <cuda_runtime.h>
#include <cuda_fp16.h>
#include <math.h>

#define L     4096
#define BATCH 16
#define CH    512     // H*E = 8*64
#define TOPK  24      // int(3.0 * ln(4096)) = 24
#define FPSCALE 1048576.0f   // 2^20 fixed point for deterministic accumulation
#define CPB   8       // channels per CTA in k_fft
#define PAD(i) ((i) + ((i) >> 4))
#define PBUF  4352    // PAD(4095)=4350 -> 4352 float2

// ---------------- scratch (device globals; no allocs) ----------------
__device__ __half2   d_z[(size_t)BATCH * CH * L];   // packed z = q + i*k (fp16), (B,C,L)
__device__ long long d_S[BATCH * L * 2];            // per-b cross spectrum (f<=2048 used)
__device__ float2    d_tw[L];                       // e^{-2pi i m / L}
__device__ float     d_mean[BATCH * L];
__device__ int       d_idx[TOPK];
__device__ float     d_w[BATCH * TOPK];
__device__ int       d_done;                        // irfft completion counter

// ---------------- complex helpers ----------------
__device__ __forceinline__ float2 cadd(float2 a, float2 b){ return make_float2(a.x+b.x, a.y+b.y); }
__device__ __forceinline__ float2 csub(float2 a, float2 b){ return make_float2(a.x-b.x, a.y-b.y); }
__device__ __forceinline__ float2 cmul(float2 a, float2 b){
    return make_float2(a.x*b.x - a.y*b.y, a.x*b.y + a.y*b.x);
}

// ---------------- K1: transpose (B,L,C)->(B,C,L) + fused init ----------------
__global__ void k_transpose(const float* __restrict__ q, const float* __restrict__ k) {
    __shared__ __half2 tile[32][33];   // [t_local][c_local], padded
    int b  = blockIdx.z;
    int t0 = blockIdx.x * 32;
    int c0 = blockIdx.y * 32;
    int tx = threadIdx.x, ty = threadIdx.y;
    int tid = ty * 32 + tx;

    // fused init: y==0 blocks zero d_S; block (0,0,0) builds twiddles + counter
    if (blockIdx.y == 0) {
        int blk = blockIdx.x + (L / 32) * blockIdx.z;   // 0..2047
        int gid = blk * 256 + tid;
        if (gid < BATCH * L * 2) d_S[gid] = 0;
        if (blk == 0) {
            for (int i = tid; i < L; i += 256) {
                double th = -2.0 * 3.14159265358979323846 * (double)i / (double)L;
                d_tw[i] = make_float2((float)cos(th), (float)sin(th));
            }
            if (tid == 0) d_done = 0;
        }
    }

    #pragma unroll
    for (int r = 0; r < 4; r++) {
        int t = t0 + ty + r * 8;
        size_t idx = ((size_t)b * L + t) * CH + c0 + tx;   // coalesced over c
        tile[ty + r * 8][tx] = __floats2half2_rn(q[idx], k[idx]);
    }
    __syncthreads();
    #pragma unroll
    for (int r = 0; r < 4; r++) {
        int c = c0 + ty + r * 8;
        d_z[((size_t)b * CH + c) * L + t0 + tx] = tile[tx][ty + r * 8];  // coalesced over t
    }
}

// ---------------- register-resident 16-point DFT (natural order in/out) --------
__device__ __forceinline__ void dft16(float2* a) {
    const float2 W16[10] = {
        { 1.0f, 0.0f},
        { 0.9238795325f,-0.3826834324f},
        { 0.7071067812f,-0.7071067812f},
        { 0.3826834324f,-0.9238795325f},
        { 0.0f,-1.0f},
        {-0.3826834324f,-0.9238795325f},
        {-0.7071067812f,-0.7071067812f},
        {-0.9238795325f,-0.3826834324f},
        {-1.0f, 0.0f},
        {-0.9238795325f, 0.3826834324f}
    };
    float2 bb[4][4];
    #pragma unroll
    for (int n1 = 0; n1 < 4; n1++) {
        float2 x0 = a[n1], x1 = a[n1+4], x2 = a[n1+8], x3 = a[n1+12];
        float2 apc = cadd(x0,x2), amc = csub(x0,x2);
        float2 bpd = cadd(x1,x3), bmd = csub(x1,x3);
        float2 mjb = make_float2(bmd.y, -bmd.x);   // -i*(x1-x3)
        bb[n1][0] = cadd(apc,bpd);
        bb[n1][1] = cadd(amc,mjb);
        bb[n1][2] = csub(apc,bpd);
        bb[n1][3] = csub(amc,mjb);
    }
    #pragma unroll
    for (int k1 = 0; k1 < 4; k1++) {
        float2 y0 = bb[0][k1];
        float2 y1 = cmul(bb[1][k1], W16[k1]);
        float2 y2 = cmul(bb[2][k1], W16[2*k1]);
        float2 y3 = cmul(bb[3][k1], W16[3*k1]);
        float2 apc = cadd(y0,y2), amc = csub(y0,y2);
        float2 bpd = cadd(y1,y3), bmd = csub(y1,y3);
        float2 mjb = make_float2(bmd.y, -bmd.x);
        a[k1]      = cadd(apc,bpd);
        a[k1+4]    = cadd(amc,mjb);
        a[k1+8]    = csub(apc,bpd);
        a[k1+12]   = csub(amc,mjb);
    }
}

// Stockham stage store: out[u + 15*ps + s*jj] = tw4096[jj*ps] * r[jj]
__device__ __forceinline__ void stage_store(const float2* r, float2* buf, int u, int s) {
    int ps = (u / s) * s;
    float2 P[4], A[4];
    P[0] = make_float2(1.f, 0.f);
    P[1] = d_tw[ps];
    P[2] = cmul(P[1], P[1]);
    P[3] = cmul(P[2], P[1]);
    A[0] = make_float2(1.f, 0.f);
    A[1] = d_tw[4  * ps];
    A[2] = d_tw[8  * ps];
    A[3] = d_tw[12 * ps];
    int base = u + 15 * ps;
    #pragma unroll
    for (int jj = 0; jj < 16; jj++) {
        float2 w = cmul(A[jj >> 2], P[jj & 3]);
        buf[PAD(base + s * jj)] = cmul(w, r[jj]);
    }
}

// ---------------- K2: pipelined FFT + half-spectrum accumulate ----------------
// Stage-2 output is register-resident: X[tid+256*j] == r[j]. Only the upper half
// (slots 2048..4095 = r[8..15]) is stored to smem, to serve Hermitian mirrors.
__global__ void __launch_bounds__(256, 3) k_fft() {
    extern __shared__ float2 sm[];
    float2* bufA = sm;
    float2* bufB = sm + PBUF;
    int tid = threadIdx.x;
    int blk = blockIdx.x;            // 1024 blocks = 16 b * 64 groups
    int b   = blk >> 6;
    int c0  = (blk & 63) * CPB;

    float accx[8], accy[8], accN = 0.f;
    #pragma unroll
    for (int j = 0; j < 8; j++) { accx[j] = 0.f; accy[j] = 0.f; }

    const __half2* zbase = d_z + ((size_t)(b * CH + c0)) * L;
    float2 r[16];
    // prologue: load channel 0
    #pragma unroll
    for (int j = 0; j < 16; j++) r[j] = __half22float2(zbase[tid + 256 * j]);

    for (int cc = 0; cc < CPB; cc++) {
        float2* X = (cc & 1) ? bufB : bufA;   // parity ping-pong
        float2* Y = (cc & 1) ? bufA : bufB;
        // stage 0 (s=1): r (preloaded) -> X
        dft16(r);
        stage_store(r, X, tid, 1);
        __syncthreads();
        // stage 1 (s=16): X -> Y
        #pragma unroll
        for (int j = 0; j < 16; j++) r[j] = X[PAD(tid + 256 * j)];
        dft16(r);
        stage_store(r, Y, tid, 16);
        __syncthreads();
        // stage 2 (s=256, ps=0, twiddles=1): Y -> regs; r[j] == X[tid+256*j]
        #pragma unroll
        for (int j = 0; j < 16; j++) r[j] = Y[PAD(tid + 256 * j)];
        dft16(r);
        if (tid == 0) accN += r[8].x * r[8].y;     // Nyquist X[2048], own reg
        // store upper half only (mirror source for f in [1,2047])
        #pragma unroll
        for (int jj = 8; jj < 16; jj++) X[PAD(tid + 256 * jj)] = r[jj];
        __syncthreads();
        // prefetch next channel's upper regs (dead after store)
        if (cc + 1 < CPB) {
            const __half2* zr = zbase + ((size_t)(cc + 1)) * L;
            #pragma unroll
            for (int j = 8; j < 16; j++) r[j] = __half22float2(zr[tid + 256 * j]);
        }
        // unpack z=q+ik for f in [0,2047]: Zf from regs, Zr from stored upper half
        #pragma unroll
        for (int j = 0; j < 8; j++) {
            int i = tid + 256 * j;                 // 0..2047
            float2 Zf = r[j];
            int m = (L - i) & (L - 1);             // 4096-i (>=2048 for i>=1)
            float2 Zr = X[PAD(m)];
            if (i == 0) Zr = Zf;                   // f=0 self-mirror
            float qx = 0.5f * (Zf.x + Zr.x), qy =  0.5f * (Zf.y - Zr.y);
            float kx = 0.5f * (Zf.y + Zr.y), ky = -0.5f * (Zf.x - Zr.x);
            accx[j] += qx * kx + qy * ky;
            accy[j] += qy * kx - qx * ky;
        }
        // prefetch next channel's lower regs
        if (cc + 1 < CPB) {
            const __half2* zr = zbase + ((size_t)(cc + 1)) * L;
            #pragma unroll
            for (int j = 0; j < 8; j++) r[j] = __half22float2(zr[tid + 256 * j]);
        }
        // no trailing sync: next stage0 writes the OTHER buffer; its post-store
        // sync orders stage1's write to this buffer after all unpack reads.
    }

    long long* Sb = d_S + b * L * 2;
    #pragma unroll
    for (int j = 0; j < 8; j++) {
        int i = tid + 256 * j;
        atomicAdd((unsigned long long*)&Sb[2 * i],
                  (unsigned long long)(long long)llrintf(accx[j] * FPSCALE));
        atomicAdd((unsigned long long*)&Sb[2 * i + 1],
                  (unsigned long long)(long long)llrintf(accy[j] * FPSCALE));
    }
    if (tid == 0)
        atomicAdd((unsigned long long*)&Sb[2 * 2048],
                  (unsigned long long)(long long)llrintf(accN * FPSCALE));
}

// ---------------- radix-4 Stockham FFT (for K3; 16 CTAs, negligible) ------
__device__ __forceinline__ void fft4096_r4(float2* x0, float2* y0,
                                           const float2* __restrict__ tw, int tid) {
    float2* x = x0;
    float2* y = y0;
    #pragma unroll
    for (int stage = 0; stage < 6; stage++) {
        int s = 1 << (2 * stage);
        #pragma unroll
        for (int uu = 0; uu < 4; uu++) {
            int u  = tid + uu * 256;
            int ps = u & ~(s - 1);
            float2 a = x[u];
            float2 b = x[u + 1024];
            float2 c = x[u + 2048];
            float2 d = x[u + 3072];
            float2 apc = cadd(a, c), amc = csub(a, c);
            float2 bpd = cadd(b, d), bmd = csub(b, d);
            float2 jbmd = make_float2(-bmd.y, bmd.x);
            float2 w1 = tw[ps], w2 = tw[2 * ps], w3 = tw[3 * ps];
            int o = u + 3 * ps;
            y[o]         = cadd(apc, bpd);
            y[o + s]     = cmul(w1, csub(amc, jbmd));
            y[o + 2 * s] = cmul(w2, csub(apc, bpd));
            y[o + 3 * s] = cmul(w3, cadd(amc, jbmd));
        }
        __syncthreads();
        float2* t = x; x = y; y = t;
    }
}

// ---------------- K3: inverse transform -> mean_value; last CTA does top-k -----
__global__ void k_irfft_topk() {
    extern __shared__ float2 sm[];
    float2* A   = sm;
    float2* B   = sm + L;
    float2* tws = sm + 2 * L;
    int tid = threadIdx.x;
    int b   = blockIdx.x;
    const long long* Sb = d_S + b * L * 2;
    const float c1 = 1.0f / FPSCALE;
    for (int i = tid; i < L; i += 256) {
        int m = (i <= 2048) ? i : (L - i);       // stored half-spectrum index
        float sx = (float)Sb[2 * m]     * c1;
        float sy = (float)Sb[2 * m + 1] * c1;
        float sgn = (i <= 2048) ? -1.f : 1.f;    // feed A = conj(S[i])
        A[i] = make_float2(sx, sgn * sy);
        tws[i] = d_tw[i];
    }
    __syncthreads();
    fft4096_r4(A, B, tws, tid);
    const float c2 = 1.0f / ((float)L * (float)CH);
    for (int i = tid; i < L; i += 256) d_mean[b * L + i] = A[i].x * c2;

    // completion counter; last CTA runs top-k + softmax
    __threadfence();
    __syncthreads();
    __shared__ int slast;
    if (tid == 0) slast = atomicAdd(&d_done, 1);
    __syncthreads();
    if (slast != BATCH - 1) return;
    __threadfence();

    float* cm = (float*)B;                      // reuse 32 KB of dynamic smem
    __shared__ float rv[256];
    __shared__ int   ri[256];
    __shared__ int   sidx[TOPK];
    for (int i = tid; i < L; i += 256) {
        float s = 0.0f;
        #pragma unroll
        for (int bb = 0; bb < BATCH; bb++) s += d_mean[bb * L + i];
        cm[i] = s;
    }
    __syncthreads();
    for (int it = 0; it < TOPK; it++) {
        float best = -1e30f; int bi = 0;
        for (int i = tid; i < L; i += 256) {
            float vv = cm[i];
            if (vv > best) { best = vv; bi = i; }
        }
        rv[tid] = best; ri[tid] = bi;
        __syncthreads();
        for (int off = 128; off > 0; off >>= 1) {
            if (tid < off) {
                if (rv[tid + off] > rv[tid] ||
                    (rv[tid + off] == rv[tid] && ri[tid + off] < ri[tid])) {
                    rv[tid] = rv[tid + off]; ri[tid] = ri[tid + off];
                }
            }
            __syncthreads();
        }
        if (tid == 0) { sidx[it] = ri[0]; cm[ri[0]] = -1e30f; }
        __syncthreads();
    }
    if (tid < TOPK) d_idx[tid] = sidx[tid];
    if (tid < BATCH) {
        int bb = tid;
        float vals[TOPK]; float mx = -1e30f;
        #pragma unroll
        for (int i = 0; i < TOPK; i++) { vals[i] = d_mean[bb * L + sidx[i]]; mx = fmaxf(mx, vals[i]); }
        float ssum = 0.0f;
        #pragma unroll
        for (int i = 0; i < TOPK; i++) { vals[i] = expf(vals[i] - mx); ssum += vals[i]; }
        #pragma unroll
        for (int i = 0; i < TOPK; i++) d_w[bb * TOPK + i] = vals[i] / ssum;
    }
}

// ---------------- K5: weighted shifted aggregation (coalesced L2 streaming) ----
__global__ void k_agg(const float4* __restrict__ v4, float4* __restrict__ o4) {
    __shared__ int   si[TOPK];
    __shared__ float sw[TOPK];
    int t = blockIdx.x, b = blockIdx.y, tid = threadIdx.x;   // 128 threads, float4 over 512 ch
    if (tid < TOPK) { si[tid] = d_idx[tid]; sw[tid] = d_w[b * TOPK + tid]; }
    __syncthreads();
    const float4* vb = v4 + (size_t)b * L * 128;
    float4 acc = make_float4(0.f, 0.f, 0.f, 0.f);
    #pragma unroll
    for (int i = 0; i < TOPK; i++) {
        int tt = (t + si[i]) & (L - 1);
        float4 vv = vb[tt * 128 + tid];
        float w = sw[i];
        acc.x += w * vv.x; acc.y += w * vv.y; acc.z += w * vv.z; acc.w += w * vv.w;
    }
    o4[((size_t)b * L + t) * 128 + tid] = acc;
}

// ---------------- launcher ----------------
extern "C" void kernel_launch(void* const* d_in, const int* in_sizes, int n_in,
                              void* d_out, int out_size) {
    const float* q = (const float*)d_in[0];
    const float* k = (const float*)d_in[1];
    const float* v = (const float*)d_in[2];

    const int smem_fft  = 2 * PBUF * sizeof(float2);   // 69,632 B
    const int smem_ifft = 3 * L * sizeof(float2);      // 96 KB
    cudaFuncSetAttribute(k_fft,        cudaFuncAttributeMaxDynamicSharedMemorySize, smem_fft);
    cudaFuncSetAttribute(k_irfft_topk, cudaFuncAttributeMaxDynamicSharedMemorySize, smem_ifft);

    k_transpose<<<dim3(L / 32, CH / 32, BATCH), dim3(32, 8, 1)>>>(q, k); // launch 1
    k_fft<<<(BATCH * CH) / CPB, 256, smem_fft>>>();                      // launch 2
    k_irfft_topk<<<BATCH, 256, smem_ifft>>>();                           // launch 3
    k_agg<<<dim3(L, BATCH), 128>>>((const float4*)v, (float4*)d_out);    // launch 4 (ncu slot)
}

// round 16
// speedup vs baseline: 1.1308x; 1.0027x over previous
#include <cuda_runtime.h>
#include <cuda_fp16.h>
#include <math.h>

#define L     4096
#define BATCH 16
#define CH    512     // H*E = 8*64
#define TOPK  24      // int(3.0 * ln(4096)) = 24
#define FPSCALE 1048576.0f   // 2^20 fixed point for deterministic accumulation
#define CPB   4       // channels per CTA in k_fft (2048 CTAs: better wave quantization)
#define PAD(i) ((i) + ((i) >> 4))
#define PBUF  4352    // PAD(4095)=4350 -> 4352 float2
#define TPC   4       // t-values per CTA in k_agg

// ---------------- scratch (device globals; no allocs) ----------------
__device__ __half2   d_z[(size_t)BATCH * CH * L];   // packed z = q + i*k (fp16), (B,C,L)
__device__ long long d_S[BATCH * L * 2];            // per-b cross spectrum (f<=2048 used)
__device__ float2    d_tw[L];                       // e^{-2pi i m / L}
__device__ float     d_mean[BATCH * L];
__device__ int       d_idx[TOPK];
__device__ float     d_w[BATCH * TOPK];
__device__ int       d_done;                        // irfft completion counter

// ---------------- complex helpers ----------------
__device__ __forceinline__ float2 cadd(float2 a, float2 b){ return make_float2(a.x+b.x, a.y+b.y); }
__device__ __forceinline__ float2 csub(float2 a, float2 b){ return make_float2(a.x-b.x, a.y-b.y); }
__device__ __forceinline__ float2 cmul(float2 a, float2 b){
    return make_float2(a.x*b.x - a.y*b.y, a.x*b.y + a.y*b.x);
}

// ---------------- K1: transpose (B,L,C)->(B,C,L) + fused init ----------------
__global__ void k_transpose(const float* __restrict__ q, const float* __restrict__ k) {
    __shared__ __half2 tile[32][33];   // [t_local][c_local], padded
    int b  = blockIdx.z;
    int t0 = blockIdx.x * 32;
    int c0 = blockIdx.y * 32;
    int tx = threadIdx.x, ty = threadIdx.y;
    int tid = ty * 32 + tx;

    // fused init: y==0 blocks zero d_S; block (0,0,0) builds twiddles + counter
    if (blockIdx.y == 0) {
        int blk = blockIdx.x + (L / 32) * blockIdx.z;   // 0..2047
        int gid = blk * 256 + tid;
        if (gid < BATCH * L * 2) d_S[gid] = 0;
        if (blk == 0) {
            for (int i = tid; i < L; i += 256) {
                double th = -2.0 * 3.14159265358979323846 * (double)i / (double)L;
                d_tw[i] = make_float2((float)cos(th), (float)sin(th));
            }
            if (tid == 0) d_done = 0;
        }
    }

    #pragma unroll
    for (int r = 0; r < 4; r++) {
        int t = t0 + ty + r * 8;
        size_t idx = ((size_t)b * L + t) * CH + c0 + tx;   // coalesced over c
        tile[ty + r * 8][tx] = __floats2half2_rn(q[idx], k[idx]);
    }
    __syncthreads();
    #pragma unroll
    for (int r = 0; r < 4; r++) {
        int c = c0 + ty + r * 8;
        d_z[((size_t)b * CH + c) * L + t0 + tx] = tile[tx][ty + r * 8];  // coalesced over t
    }
}

// ---------------- register-resident 16-point DFT (natural order in/out) --------
__device__ __forceinline__ void dft16(float2* a) {
    const float2 W16[10] = {
        { 1.0f, 0.0f},
        { 0.9238795325f,-0.3826834324f},
        { 0.7071067812f,-0.7071067812f},
        { 0.3826834324f,-0.9238795325f},
        { 0.0f,-1.0f},
        {-0.3826834324f,-0.9238795325f},
        {-0.7071067812f,-0.7071067812f},
        {-0.9238795325f,-0.3826834324f},
        {-1.0f, 0.0f},
        {-0.9238795325f, 0.3826834324f}
    };
    float2 bb[4][4];
    #pragma unroll
    for (int n1 = 0; n1 < 4; n1++) {
        float2 x0 = a[n1], x1 = a[n1+4], x2 = a[n1+8], x3 = a[n1+12];
        float2 apc = cadd(x0,x2), amc = csub(x0,x2);
        float2 bpd = cadd(x1,x3), bmd = csub(x1,x3);
        float2 mjb = make_float2(bmd.y, -bmd.x);   // -i*(x1-x3)
        bb[n1][0] = cadd(apc,bpd);
        bb[n1][1] = cadd(amc,mjb);
        bb[n1][2] = csub(apc,bpd);
        bb[n1][3] = csub(amc,mjb);
    }
    #pragma unroll
    for (int k1 = 0; k1 < 4; k1++) {
        float2 y0 = bb[0][k1];
        float2 y1 = cmul(bb[1][k1], W16[k1]);
        float2 y2 = cmul(bb[2][k1], W16[2*k1]);
        float2 y3 = cmul(bb[3][k1], W16[3*k1]);
        float2 apc = cadd(y0,y2), amc = csub(y0,y2);
        float2 bpd = cadd(y1,y3), bmd = csub(y1,y3);
        float2 mjb = make_float2(bmd.y, -bmd.x);
        a[k1]      = cadd(apc,bpd);
        a[k1+4]    = cadd(amc,mjb);
        a[k1+8]    = csub(apc,bpd);
        a[k1+12]   = csub(amc,mjb);
    }
}

// Stockham stage store: out[u + 15*ps + s*jj] = tw4096[jj*ps] * r[jj]
__device__ __forceinline__ void stage_store(const float2* r, float2* buf, int u, int s) {
    int ps = (u / s) * s;
    float2 P[4], A[4];
    P[0] = make_float2(1.f, 0.f);
    P[1] = d_tw[ps];
    P[2] = cmul(P[1], P[1]);
    P[3] = cmul(P[2], P[1]);
    A[0] = make_float2(1.f, 0.f);
    A[1] = d_tw[4  * ps];
    A[2] = d_tw[8  * ps];
    A[3] = d_tw[12 * ps];
    int base = u + 15 * ps;
    #pragma unroll
    for (int jj = 0; jj < 16; jj++) {
        float2 w = cmul(A[jj >> 2], P[jj & 3]);
        buf[PAD(base + s * jj)] = cmul(w, r[jj]);
    }
}

// ---------------- K2: pipelined FFT + half-spectrum accumulate ----------------
// Stage-2 output is register-resident: X[tid+256*j] == r[j]. Only the upper half
// (slots 2048..4095 = r[8..15]) is stored to smem, to serve Hermitian mirrors.
__global__ void __launch_bounds__(256, 3) k_fft() {
    extern __shared__ float2 sm[];
    float2* bufA = sm;
    float2* bufB = sm + PBUF;
    int tid = threadIdx.x;
    int blk = blockIdx.x;            // 2048 blocks = 16 b * 128 groups
    int b   = blk >> 7;
    int c0  = (blk & 127) * CPB;

    float accx[8], accy[8], accN = 0.f;
    #pragma unroll
    for (int j = 0; j < 8; j++) { accx[j] = 0.f; accy[j] = 0.f; }

    const __half2* zbase = d_z + ((size_t)(b * CH + c0)) * L;
    float2 r[16];
    // prologue: load channel 0
    #pragma unroll
    for (int j = 0; j < 16; j++) r[j] = __half22float2(zbase[tid + 256 * j]);

    for (int cc = 0; cc < CPB; cc++) {
        float2* X = (cc & 1) ? bufB : bufA;   // parity ping-pong
        float2* Y = (cc & 1) ? bufA : bufB;
        // stage 0 (s=1): r (preloaded) -> X
        dft16(r);
        stage_store(r, X, tid, 1);
        __syncthreads();
        // stage 1 (s=16): X -> Y
        #pragma unroll
        for (int j = 0; j < 16; j++) r[j] = X[PAD(tid + 256 * j)];
        dft16(r);
        stage_store(r, Y, tid, 16);
        __syncthreads();
        // stage 2 (s=256, ps=0, twiddles=1): Y -> regs; r[j] == X[tid+256*j]
        #pragma unroll
        for (int j = 0; j < 16; j++) r[j] = Y[PAD(tid + 256 * j)];
        dft16(r);
        if (tid == 0) accN += r[8].x * r[8].y;     // Nyquist X[2048], own reg
        // store upper half only (mirror source for f in [1,2047])
        #pragma unroll
        for (int jj = 8; jj < 16; jj++) X[PAD(tid + 256 * jj)] = r[jj];
        __syncthreads();
        // prefetch next channel's upper regs (dead after store)
        if (cc + 1 < CPB) {
            const __half2* zr = zbase + ((size_t)(cc + 1)) * L;
            #pragma unroll
            for (int j = 8; j < 16; j++) r[j] = __half22float2(zr[tid + 256 * j]);
        }
        // unpack z=q+ik for f in [0,2047]: Zf from regs, Zr from stored upper half
        #pragma unroll
        for (int j = 0; j < 8; j++) {
            int i = tid + 256 * j;                 // 0..2047
            float2 Zf = r[j];
            int m = (L - i) & (L - 1);             // 4096-i (>=2048 for i>=1)
            float2 Zr = X[PAD(m)];
            if (i == 0) Zr = Zf;                   // f=0 self-mirror
            float qx = 0.5f * (Zf.x + Zr.x), qy =  0.5f * (Zf.y - Zr.y);
            float kx = 0.5f * (Zf.y + Zr.y), ky = -0.5f * (Zf.x - Zr.x);
            accx[j] += qx * kx + qy * ky;
            accy[j] += qy * kx - qx * ky;
        }
        // prefetch next channel's lower regs
        if (cc + 1 < CPB) {
            const __half2* zr = zbase + ((size_t)(cc + 1)) * L;
            #pragma unroll
            for (int j = 0; j < 8; j++) r[j] = __half22float2(zr[tid + 256 * j]);
        }
        // no trailing sync: next stage0 writes the OTHER buffer; its post-store
        // sync orders stage1's write to this buffer after all unpack reads.
    }

    long long* Sb = d_S + b * L * 2;
    #pragma unroll
    for (int j = 0; j < 8; j++) {
        int i = tid + 256 * j;
        atomicAdd((unsigned long long*)&Sb[2 * i],
                  (unsigned long long)(long long)llrintf(accx[j] * FPSCALE));
        atomicAdd((unsigned long long*)&Sb[2 * i + 1],
                  (unsigned long long)(long long)llrintf(accy[j] * FPSCALE));
    }
    if (tid == 0)
        atomicAdd((unsigned long long*)&Sb[2 * 2048],
                  (unsigned long long)(long long)llrintf(accN * FPSCALE));
}

// ---------------- K3: radix-16 inverse transform -> mean_value; last CTA top-k --
// mean = Re(DFT(conj(S)))/(L*CH); 3-stage pipeline, result lands in registers.
__global__ void __launch_bounds__(256, 3) k_irfft_topk() {
    extern __shared__ float2 sm[];
    float2* bufA = sm;
    float2* bufB = sm + PBUF;
    int tid = threadIdx.x;
    int b   = blockIdx.x;
    const long long* Sb = d_S + b * L * 2;
    const float c1 = 1.0f / FPSCALE;

    float2 r[16];
    #pragma unroll
    for (int j = 0; j < 16; j++) {
        int i = tid + 256 * j;
        int m = (i <= 2048) ? i : (L - i);       // stored half-spectrum index
        float sx = (float)Sb[2 * m]     * c1;
        float sy = (float)Sb[2 * m + 1] * c1;
        float sgn = (i <= 2048) ? -1.f : 1.f;    // A = conj(S[i])
        r[j] = make_float2(sx, sgn * sy);
    }
    dft16(r);
    stage_store(r, bufA, tid, 1);
    __syncthreads();
    #pragma unroll
    for (int j = 0; j < 16; j++) r[j] = bufA[PAD(tid + 256 * j)];
    dft16(r);
    stage_store(r, bufB, tid, 16);
    __syncthreads();
    #pragma unroll
    for (int j = 0; j < 16; j++) r[j] = bufB[PAD(tid + 256 * j)];
    dft16(r);                                    // r[j] = X[tid+256*j]
    const float c2 = 1.0f / ((float)L * (float)CH);
    #pragma unroll
    for (int j = 0; j < 16; j++) d_mean[b * L + tid + 256 * j] = r[j].x * c2;

    // completion counter; last CTA runs top-k + softmax
    __threadfence();
    __syncthreads();
    __shared__ int slast;
    if (tid == 0) slast = atomicAdd(&d_done, 1);
    __syncthreads();
    if (slast != BATCH - 1) return;
    __threadfence();

    float* cm = (float*)bufA;                   // reuse 16 KB of dynamic smem
    __shared__ float rv[256];
    __shared__ int   ri[256];
    __shared__ int   sidx[TOPK];
    for (int i = tid; i < L; i += 256) {
        float s = 0.0f;
        #pragma unroll
        for (int bb = 0; bb < BATCH; bb++) s += d_mean[bb * L + i];
        cm[i] = s;
    }
    __syncthreads();
    for (int it = 0; it < TOPK; it++) {
        float best = -1e30f; int bi = 0;
        for (int i = tid; i < L; i += 256) {
            float vv = cm[i];
            if (vv > best) { best = vv; bi = i; }
        }
        rv[tid] = best; ri[tid] = bi;
        __syncthreads();
        for (int off = 128; off > 0; off >>= 1) {
            if (tid < off) {
                if (rv[tid + off] > rv[tid] ||
                    (rv[tid + off] == rv[tid] && ri[tid + off] < ri[tid])) {
                    rv[tid] = rv[tid + off]; ri[tid] = ri[tid + off];
                }
            }
            __syncthreads();
        }
        if (tid == 0) { sidx[it] = ri[0]; cm[ri[0]] = -1e30f; }
        __syncthreads();
    }
    if (tid < TOPK) d_idx[tid] = sidx[tid];
    if (tid < BATCH) {
        int bb = tid;
        float vals[TOPK]; float mx = -1e30f;
        #pragma unroll
        for (int i = 0; i < TOPK; i++) { vals[i] = d_mean[bb * L + sidx[i]]; mx = fmaxf(mx, vals[i]); }
        float ssum = 0.0f;
        #pragma unroll
        for (int i = 0; i < TOPK; i++) { vals[i] = expf(vals[i] - mx); ssum += vals[i]; }
        #pragma unroll
        for (int i = 0; i < TOPK; i++) d_w[bb * TOPK + i] = vals[i] / ssum;
    }
}

// ---------------- K5: weighted shifted aggregation (coalesced, 4 t per CTA) ----
__global__ void __launch_bounds__(128) k_agg(const float4* __restrict__ v4,
                                             float4* __restrict__ o4) {
    __shared__ int   si[TOPK];
    __shared__ float sw[TOPK];
    int t0 = blockIdx.x * TPC, b = blockIdx.y, tid = threadIdx.x;
    if (tid < TOPK) { si[tid] = d_idx[tid]; sw[tid] = d_w[b * TOPK + tid]; }
    __syncthreads();
    const float4* vb = v4 + (size_t)b * L * 128;
    float4 acc[TPC];
    #pragma unroll
    for (int u = 0; u < TPC; u++) acc[u] = make_float4(0.f, 0.f, 0.f, 0.f);
    #pragma unroll
    for (int i = 0; i < TOPK; i++) {
        int   s = si[i];
        float w = sw[i];
        #pragma unroll
        for (int u = 0; u < TPC; u++) {
            int tt = (t0 + u + s) & (L - 1);
            float4 vv = vb[tt * 128 + tid];
            acc[u].x += w * vv.x; acc[u].y += w * vv.y;
            acc[u].z += w * vv.z; acc[u].w += w * vv.w;
        }
    }
    #pragma unroll
    for (int u = 0; u < TPC; u++)
        o4[((size_t)b * L + t0 + u) * 128 + tid] = acc[u];
}

// ---------------- launcher ----------------
extern "C" void kernel_launch(void* const* d_in, const int* in_sizes, int n_in,
                              void* d_out, int out_size) {
    const float* q = (const float*)d_in[0];
    const float* k = (const float*)d_in[1];
    const float* v = (const float*)d_in[2];

    const int smem_fft = 2 * PBUF * sizeof(float2);   // 69,632 B
    cudaFuncSetAttribute(k_fft,        cudaFuncAttributeMaxDynamicSharedMemorySize, smem_fft);
    cudaFuncSetAttribute(k_irfft_topk, cudaFuncAttributeMaxDynamicSharedMemorySize, smem_fft);

    k_transpose<<<dim3(L / 32, CH / 32, BATCH), dim3(32, 8, 1)>>>(q, k); // launch 1
    k_fft<<<(BATCH * CH) / CPB, 256, smem_fft>>>();                      // launch 2
    k_irfft_topk<<<BATCH, 256, smem_fft>>>();                            // launch 3
    k_agg<<<dim3(L / TPC, BATCH), 128>>>((const float4*)v, (float4*)d_out); // launch 4 (ncu slot)
}